// round 3
// baseline (speedup 1.0000x reference)
#include <cuda_runtime.h>
#include <math.h>

// B=8, M=256, E=128, K=16, H=1024, A=256, R=1024, RMS=512
#define NEGV (-1e25f)

typedef unsigned long long u64;

// ---------------- scratch (device globals) ----------------
__device__ float g_W2[512 * 1024];     // concat(Wv, Wu) rows
__device__ float g_b2[512];            // concat(bv, bu)
__device__ float g_Y[2048 * 512];      // gate pre-activations [2048, 512] (V | U)
__device__ float g_scores[2048];       // per-mention attention logit
__device__ float g_cat[1024 * 1536];   // [B*E, H+RMS]
__device__ float g_sw[1024 * 1024];    // RM @ Wr^T + br
__device__ float g_s1[1024 * 1024];    // entity_reprs @ sw^T
__device__ float g_s2p[2 * 1024 * 512];// split-K partials for s2
__device__ float g_RMT[512 * 1024];    // relation_memory^T

// ---------------- f32x2 helpers ----------------
__device__ __forceinline__ u64 pack2(float lo, float hi) {
    u64 r;
    asm("mov.b64 %0, {%1, %2};" : "=l"(r) : "f"(lo), "f"(hi));
    return r;
}
__device__ __forceinline__ void unpack2(u64 v, float& lo, float& hi) {
    asm("mov.b64 {%0, %1}, %2;" : "=f"(lo), "=f"(hi) : "l"(v));
}
__device__ __forceinline__ void fma2(u64& d, u64 a, u64 b) {
    asm("fma.rn.f32x2 %0, %1, %2, %0;" : "+l"(d) : "l"(a), "l"(b));
}

// ---------------- NT GEMM, f32x2 packed: C[M,N] = A[M,K] @ B[N,K]^T (+bias) -----
// Block tile 128x64, BK=16, 256 threads. Thread tile: 8 rows (4 f32x2 pairs) x 4 cols.
// Optional K-split over gridDim.z (A,B advance by z*K cols; C advances z*zstride).
#define BM 128
#define BN 64
#define BK 16

__global__ void __launch_bounds__(256) gemm_nt_f32x2(
    const float* __restrict__ A, const float* __restrict__ B,
    float* __restrict__ C, const float* __restrict__ bias,
    int K, int lda, int ldb, int ldc, int zstride)
{
    __shared__ __align__(16) float As[BK][BM];   // k-major A tile (row pairs contiguous)
    __shared__ __align__(16) u64 Bs2[BK][4][16]; // duplicated (b,b); [k][j][tx]

    const int tid = threadIdx.x;
    const int row0 = blockIdx.y * BM;
    const int col0 = blockIdx.x * BN;
    const int z = blockIdx.z;

    A += (size_t)z * K;                 // K-split column offset
    B += (size_t)z * K;
    C += (size_t)z * zstride;

    const int tx = tid & 15;            // col group (4 cols)
    const int ty = tid >> 4;            // row group (8 rows)

    // A tile load mapping: 8 floats/thread
    const int alr = tid >> 1;           // 0..127
    const int alk = (tid & 1) * 8;      // 0 or 8
    const float* Ap = A + (size_t)(row0 + alr) * lda + alk;

    // B tile load mapping: 4 floats/thread
    const int blr = tid >> 2;           // 0..63 (N row)
    const int blk = (tid & 3) * 4;      // k offset
    const float* Bp = B + (size_t)(col0 + blr) * ldb + blk;
    const int bj = blr & 3;
    const int bt = blr >> 2;

    u64 acc[4][4];
#pragma unroll
    for (int i = 0; i < 4; i++)
#pragma unroll
        for (int j = 0; j < 4; j++) acc[i][j] = 0ull;  // (0.0f, 0.0f)

    for (int k0 = 0; k0 < K; k0 += BK) {
        float4 a0 = *(const float4*)(Ap + k0);
        float4 a1 = *(const float4*)(Ap + k0 + 4);
        float4 b0 = *(const float4*)(Bp + k0);

        As[alk + 0][alr] = a0.x;
        As[alk + 1][alr] = a0.y;
        As[alk + 2][alr] = a0.z;
        As[alk + 3][alr] = a0.w;
        As[alk + 4][alr] = a1.x;
        As[alk + 5][alr] = a1.y;
        As[alk + 6][alr] = a1.z;
        As[alk + 7][alr] = a1.w;

        Bs2[blk + 0][bj][bt] = pack2(b0.x, b0.x);
        Bs2[blk + 1][bj][bt] = pack2(b0.y, b0.y);
        Bs2[blk + 2][bj][bt] = pack2(b0.z, b0.z);
        Bs2[blk + 3][bj][bt] = pack2(b0.w, b0.w);
        __syncthreads();

#pragma unroll
        for (int kk = 0; kk < BK; kk++) {
            ulonglong2 a01 = *(const ulonglong2*)&As[kk][ty * 8];
            ulonglong2 a23 = *(const ulonglong2*)&As[kk][ty * 8 + 4];
            u64 av0 = a01.x, av1 = a01.y, av2 = a23.x, av3 = a23.y;
            u64 bv0 = Bs2[kk][0][tx];
            u64 bv1 = Bs2[kk][1][tx];
            u64 bv2 = Bs2[kk][2][tx];
            u64 bv3 = Bs2[kk][3][tx];
            fma2(acc[0][0], av0, bv0); fma2(acc[0][1], av0, bv1);
            fma2(acc[0][2], av0, bv2); fma2(acc[0][3], av0, bv3);
            fma2(acc[1][0], av1, bv0); fma2(acc[1][1], av1, bv1);
            fma2(acc[1][2], av1, bv2); fma2(acc[1][3], av1, bv3);
            fma2(acc[2][0], av2, bv0); fma2(acc[2][1], av2, bv1);
            fma2(acc[2][2], av2, bv2); fma2(acc[2][3], av2, bv3);
            fma2(acc[3][0], av3, bv0); fma2(acc[3][1], av3, bv1);
            fma2(acc[3][2], av3, bv2); fma2(acc[3][3], av3, bv3);
        }
        __syncthreads();
    }

    float4 bb = make_float4(0.f, 0.f, 0.f, 0.f);
    if (bias) bb = *(const float4*)&bias[col0 + tx * 4];

#pragma unroll
    for (int i = 0; i < 4; i++) {
        float lo0, hi0, lo1, hi1, lo2, hi2, lo3, hi3;
        unpack2(acc[i][0], lo0, hi0);
        unpack2(acc[i][1], lo1, hi1);
        unpack2(acc[i][2], lo2, hi2);
        unpack2(acc[i][3], lo3, hi3);
        int r = row0 + ty * 8 + 2 * i;
        float4 c0 = make_float4(lo0 + bb.x, lo1 + bb.y, lo2 + bb.z, lo3 + bb.w);
        float4 c1 = make_float4(hi0 + bb.x, hi1 + bb.y, hi2 + bb.z, hi3 + bb.w);
        *(float4*)&C[(size_t)r * ldc + col0 + tx * 4] = c0;
        *(float4*)&C[(size_t)(r + 1) * ldc + col0 + tx * 4] = c1;
    }
}

// ---------------- weight concat: W2 = [Wv; Wu], b2 = [bv; bu] --------------------
__global__ void concat_w_kernel(const float* __restrict__ Wv, const float* __restrict__ Wu,
                                const float* __restrict__ bv, const float* __restrict__ bu,
                                float* __restrict__ W2, float* __restrict__ b2)
{
    int i = blockIdx.x * blockDim.x + threadIdx.x;   // float4 index over 512*1024/4
    const float4* src = (i < 65536) ? (const float4*)Wv : (const float4*)Wu - 65536;
    ((float4*)W2)[i] = src[i];
    if (i < 128) {
        ((float4*)b2)[i] = (i < 64) ? ((const float4*)bv)[i] : ((const float4*)bu)[i - 64];
    }
}

// ---------------- per-mention gate score reduction -------------------------------
__global__ void score_reduce_kernel(const float* __restrict__ Y,
                                    const float* __restrict__ Wa, const float* __restrict__ ba,
                                    float* __restrict__ scores)
{
    const int row = blockIdx.x;   // 0..2047
    const int a = threadIdx.x;    // 0..255
    float v = tanhf(Y[row * 512 + a]);
    float u = 1.f / (1.f + expf(-Y[row * 512 + 256 + a]));
    float c = v * u * Wa[a];

    __shared__ float wsum[8];
#pragma unroll
    for (int o = 16; o > 0; o >>= 1) c += __shfl_down_sync(0xffffffffu, c, o);
    if ((a & 31) == 0) wsum[a >> 5] = c;
    __syncthreads();
    if (a == 0) {
        float s = 0.f;
#pragma unroll
        for (int i = 0; i < 8; i++) s += wsum[i];
        scores[row] = s + ba[0];
    }
}

// ---------------- masked softmax over K + weighted pooling -----------------------
__global__ void attn_pool_kernel(const float* __restrict__ X, const int* __restrict__ ent,
                                 const int* __restrict__ msk, const float* __restrict__ scores,
                                 float* __restrict__ cat)
{
    const int be = blockIdx.x;    // 0..1023
    const int b = be >> 7;
    const int tid = threadIdx.x;  // 256

    __shared__ int sidx[16];
    __shared__ float w[16];

    if (tid < 16) {
        int idx = ent[be * 16 + tid];
        int m = msk[be * 16 + tid];
        sidx[tid] = idx;
        w[tid] = m ? scores[b * 256 + idx] : NEGV;
    }
    __syncthreads();
    if (tid == 0) {
        float mx = w[0];
#pragma unroll
        for (int k = 1; k < 16; k++) mx = fmaxf(mx, w[k]);
        float e[16];
        float sum = 0.f;
#pragma unroll
        for (int k = 0; k < 16; k++) { e[k] = expf(w[k] - mx); sum += e[k]; }
        float inv = 1.f / sum;
#pragma unroll
        for (int k = 0; k < 16; k++) w[k] = e[k] * inv;
    }
    __syncthreads();

    float4 acc = make_float4(0.f, 0.f, 0.f, 0.f);
    const float4* Xb = (const float4*)(X + (size_t)b * 256 * 1024);
#pragma unroll
    for (int k = 0; k < 16; k++) {
        float wk = w[k];
        float4 x = Xb[sidx[k] * 256 + tid];
        acc.x += wk * x.x; acc.y += wk * x.y; acc.z += wk * x.z; acc.w += wk * x.w;
    }
    *(float4*)&cat[(size_t)be * 1536 + tid * 4] = acc;
}

// ---------------- transpose relation_memory [1024,512] -> [512,1024] -------------
__global__ void transpose_kernel(const float* __restrict__ RM, float* __restrict__ RMT)
{
    __shared__ float tile[32][33];
    int x = blockIdx.x * 32 + threadIdx.x;
    int y = blockIdx.y * 32 + threadIdx.y;
#pragma unroll
    for (int j = 0; j < 32; j += 8)
        tile[threadIdx.y + j][threadIdx.x] = RM[(size_t)(y + j) * 512 + x];
    __syncthreads();
    int ox = blockIdx.y * 32 + threadIdx.x;
    int oy = blockIdx.x * 32 + threadIdx.y;
#pragma unroll
    for (int j = 0; j < 32; j += 8)
        RMT[(size_t)(oy + j) * 1024 + ox] = tile[threadIdx.x][threadIdx.y + j];
}

// ---------------- s2 split-K merge: cat[:,1024:] = p0 + p1 -----------------------
__global__ void add_s2_kernel(const float* __restrict__ p, float* __restrict__ cat)
{
    int i = blockIdx.x * blockDim.x + threadIdx.x;   // over 1024*512/4 float4s
    int row = i >> 7;           // 128 float4 per row
    int col = i & 127;
    float4 a = ((const float4*)p)[i];
    float4 b = ((const float4*)p)[i + 131072];
    float4 c = make_float4(a.x + b.x, a.y + b.y, a.z + b.z, a.w + b.w);
    *(float4*)&cat[(size_t)row * 1536 + 1024 + col * 4] = c;
}

// ---------------- launch ---------------------------------------------------------
extern "C" void kernel_launch(void* const* d_in, const int* in_sizes, int n_in,
                              void* d_out, int out_size)
{
    const float* X   = (const float*)d_in[0];
    const int*   ent = (const int*)d_in[1];
    const int*   msk = (const int*)d_in[2];
    const float* RM  = (const float*)d_in[3];
    const float* Wv  = (const float*)d_in[4];
    const float* bv  = (const float*)d_in[5];
    const float* Wu  = (const float*)d_in[6];
    const float* bu  = (const float*)d_in[7];
    const float* Wa  = (const float*)d_in[8];
    const float* ba  = (const float*)d_in[9];
    const float* Wr  = (const float*)d_in[10];
    const float* br  = (const float*)d_in[11];
    const float* Wo  = (const float*)d_in[12];
    const float* bo  = (const float*)d_in[13];
    float* out = (float*)d_out;

    float *W2, *b2, *Y, *scores, *cat, *sw, *s1, *s2p, *rmt;
    cudaGetSymbolAddress((void**)&W2, g_W2);
    cudaGetSymbolAddress((void**)&b2, g_b2);
    cudaGetSymbolAddress((void**)&Y, g_Y);
    cudaGetSymbolAddress((void**)&scores, g_scores);
    cudaGetSymbolAddress((void**)&cat, g_cat);
    cudaGetSymbolAddress((void**)&sw, g_sw);
    cudaGetSymbolAddress((void**)&s1, g_s1);
    cudaGetSymbolAddress((void**)&s2p, g_s2p);
    cudaGetSymbolAddress((void**)&rmt, g_RMT);

    // 0) concat gate weights
    concat_w_kernel<<<512, 256>>>(Wv, Wu, bv, bu, W2, b2);

    // 1) merged gate GEMM: Y [2048,512] = X @ W2^T + b2
    gemm_nt_f32x2<<<dim3(512 / BN, 2048 / BM), 256>>>(X, W2, Y, b2, 1024, 1024, 1024, 512, 0);

    // 2) per-mention logit
    score_reduce_kernel<<<2048, 256>>>(Y, Wa, ba, scores);

    // 3) masked softmax + pooling -> cat[:, :1024]
    attn_pool_kernel<<<1024, 256>>>(X, ent, msk, scores, cat);

    // 4) RM^T
    transpose_kernel<<<dim3(16, 32), dim3(32, 8)>>>(RM, rmt);

    // 5) sw [1024,1024] = RM @ Wr^T + br
    gemm_nt_f32x2<<<dim3(1024 / BN, 1024 / BM), 256>>>(RM, Wr, sw, br, 512, 512, 512, 1024, 0);

    // 6) s1 [1024,1024] = entity_reprs @ sw^T
    gemm_nt_f32x2<<<dim3(1024 / BN, 1024 / BM), 256>>>(cat, sw, s1, nullptr, 1024, 1536, 1024, 1024, 0);

    // 7) s2 partials [2][1024,512] = s1 @ RMT^T, split-K over z
    gemm_nt_f32x2<<<dim3(512 / BN, 1024 / BM, 2), 256>>>(s1, rmt, s2p, nullptr, 512, 1024, 1024, 512, 1024 * 512);

    // 7b) merge partials into cat[:, 1024:]
    add_s2_kernel<<<512, 256>>>(s2p, cat);

    // 8) out [1024,1024] = cat @ Wo^T + bo
    gemm_nt_f32x2<<<dim3(1024 / BN, 1024 / BM), 256>>>(cat, Wo, out, bo, 1536, 1536, 1536, 1024, 0);
}